// round 17
// baseline (speedup 1.0000x reference)
#include <cuda_runtime.h>
#include <cub/block/block_radix_sort.cuh>
#include <cstdint>

#define N     4096
#define DX    512
#define DZ    64
#define KDIV  32.0
#define LPAIR 0.5

#define BM   128
#define BN   128
#define BKS  16
#define TN   (N / BM)
#define NBLK (TN * (TN + 1) / 2)

// ---------------- scratch ---------------------------------------------------
__device__ float              g_dist_x[(size_t)N * N];
__device__ float              g_dist_z[(size_t)N * N];
__device__ float              g_xt[(size_t)DX * N];   // x transposed [DX][N]
__device__ float              g_zt[(size_t)DZ * N];   // z transposed [DZ][N]
__device__ float              g_norm[2][N];
__device__ unsigned           g_maxbits[2];
__device__ double             g_partials[N];
__device__ unsigned long long g_ranksum;

// ---------------- fused transpose (x and z) + init --------------------------
__global__ void transpose_kernel(const float* __restrict__ X,
                                 const float* __restrict__ Z) {
    if (blockIdx.x == 0 && blockIdx.y == 0 && threadIdx.x == 0 && threadIdx.y == 0) {
        g_maxbits[0] = 0u;
        g_maxbits[1] = 0u;
        g_ranksum    = 0ull;
    }
    __shared__ float t[32][33];
    const int zsel = (blockIdx.x >= DX / 32) ? 1 : 0;
    const int bx   = zsel ? (blockIdx.x - DX / 32) : blockIdx.x;
    const float* in = zsel ? Z : X;
    float* out      = zsel ? g_zt : g_xt;
    const int C     = zsel ? DZ : DX;

    int x = bx * 32 + threadIdx.x;
    int y = blockIdx.y * 32 + threadIdx.y;
#pragma unroll
    for (int j = 0; j < 32; j += 8)
        t[threadIdx.y + j][threadIdx.x] = in[(size_t)(y + j) * C + x];
    __syncthreads();
    x = blockIdx.y * 32 + threadIdx.x;
    y = bx * 32 + threadIdx.y;
#pragma unroll
    for (int j = 0; j < 32; j += 8)
        out[(size_t)(y + j) * N + x] = t[threadIdx.x][threadIdx.y + j];
}

// ---------------- fused row squared norms (x rows then z rows) --------------
__global__ void norms_kernel(const float* __restrict__ X,
                             const float* __restrict__ Z) {
    const int b   = blockIdx.x;
    const int sel = (b >= N) ? 1 : 0;
    const int row = sel ? (b - N) : b;
    const int D   = sel ? DZ : DX;
    const float* a = (sel ? Z : X) + (size_t)row * D;
    float s = 0.f;
    for (int k = threadIdx.x; k < D; k += 128) {
        float v = a[k];
        s += v * v;
    }
    __shared__ float red[128];
    red[threadIdx.x] = s;
    __syncthreads();
    for (int off = 64; off > 0; off >>= 1) {
        if (threadIdx.x < off) red[threadIdx.x] += red[threadIdx.x + off];
        __syncthreads();
    }
    if (threadIdx.x == 0) g_norm[sel][row] = red[0];
}

// ---------------- fused cp.async 2-stage pipelined fp32 dist kernel ---------
#define FMA_F32X2(acc, a, b)                                                  \
    asm("fma.rn.f32x2 %0, %1, %2, %3;"                                         \
        : "=l"(acc) : "l"(a), "l"(b), "l"(acc))

__device__ __forceinline__ void unpack_f32x2(unsigned long long v, float& lo, float& hi) {
    asm("mov.b64 {%0, %1}, %2;" : "=f"(lo), "=f"(hi) : "l"(v));
}

#define CP_ASYNC16(saddr, gptr)                                               \
    asm volatile("cp.async.cg.shared.global [%0], [%1], 16;"                  \
                 :: "r"(saddr), "l"(gptr))
#define CP_COMMIT()  asm volatile("cp.async.commit_group;")
#define CP_WAIT(n)   asm volatile("cp.async.wait_group %0;" :: "n"(n))

__global__ __launch_bounds__(256, 2) void dist_kernel() {
    __shared__ __align__(16) float sA[2][BKS][BM];
    __shared__ __align__(16) float sB[2][BKS][BN];
    __shared__ float fred[256];

    const int which = (blockIdx.x >= NBLK) ? 1 : 0;
    int rem = blockIdx.x - (which ? NBLK : 0);

    const float* XT    = which ? g_zt : g_xt;          // [D][N]
    float* dist        = which ? g_dist_z : g_dist_x;
    const float* norms = g_norm[which];
    const int D        = which ? DZ : DX;

    int by = 0, width = TN;
    while (rem >= width) { rem -= width; by++; width--; }
    const int bx = by + rem;

    const int tid = threadIdx.x;
    const int tx  = tid & 15;
    const int ty  = tid >> 4;
    const int x0  = bx * BN;
    const int y0  = by * BM;

    unsigned long long acc2[8][4];
#pragma unroll
    for (int i = 0; i < 8; i++)
#pragma unroll
        for (int p = 0; p < 4; p++) acc2[i][p] = 0ull;

    auto load_tile = [&](int buf, int t) {
        const int k0 = t * BKS;
#pragma unroll
        for (int it = 0; it < 4; it++) {
            int idx  = tid + it * 256;
            int half = idx >> 9;
            int c    = idx & 511;
            int kk   = c >> 5;
            int seg  = c & 31;
            const float* src = XT + (size_t)(k0 + kk) * N +
                               (half ? x0 : y0) + seg * 4;
            float* dstp = half ? &sB[buf][kk][seg * 4] : &sA[buf][kk][seg * 4];
            uint32_t sa = (uint32_t)__cvta_generic_to_shared(dstp);
            CP_ASYNC16(sa, src);
        }
        CP_COMMIT();
    };

    const int T = D / BKS;
    load_tile(0, 0);

    for (int t = 0; t < T; t++) {
        if (t + 1 < T) {
            load_tile((t + 1) & 1, t + 1);
            CP_WAIT(1);
        } else {
            CP_WAIT(0);
        }
        __syncthreads();

        const float (*Ab)[BM] = sA[t & 1];
        const float (*Bb)[BN] = sB[t & 1];
#pragma unroll
        for (int k = 0; k < BKS; k++) {
            float4 a0 = *(const float4*)&Ab[k][ty * 8];
            float4 a1 = *(const float4*)&Ab[k][ty * 8 + 4];
            float4 b0 = *(const float4*)&Bb[k][tx * 4];
            float4 b1 = *(const float4*)&Bb[k][64 + tx * 4];
            unsigned long long bp[4];
            const unsigned long long* b0p = (const unsigned long long*)&b0;
            const unsigned long long* b1p = (const unsigned long long*)&b1;
            bp[0] = b0p[0]; bp[1] = b0p[1]; bp[2] = b1p[0]; bp[3] = b1p[1];
            float av[8] = {a0.x, a0.y, a0.z, a0.w, a1.x, a1.y, a1.z, a1.w};
#pragma unroll
            for (int i = 0; i < 8; i++) {
                unsigned long long ad;
                asm("mov.b64 %0, {%1, %1};" : "=l"(ad) : "f"(av[i]));
#pragma unroll
                for (int p = 0; p < 4; p++) FMA_F32X2(acc2[i][p], ad, bp[p]);
            }
        }
        __syncthreads();
    }

    // ---- epilogue: per 4-column group, direct float4 + mirror float4 -------
    float tmax = 0.f;
    const bool offdiag = (bx != by);

#pragma unroll
    for (int g = 0; g < 2; g++) {
        const int colg = x0 + (g ? 64 + tx * 4 : tx * 4);
        float nc0 = norms[colg + 0], nc1 = norms[colg + 1];
        float nc2 = norms[colg + 2], nc3 = norms[colg + 3];
        float tcol[4][8];                         // [j][i] for mirror
#pragma unroll
        for (int i = 0; i < 8; i++) {
            int   r  = y0 + ty * 8 + i;
            float nr = norms[r];
            float g0, g1, g2, g3;
            unpack_f32x2(acc2[i][g * 2 + 0], g0, g1);
            unpack_f32x2(acc2[i][g * 2 + 1], g2, g3);
            float sq0 = fmaxf(nr + nc0 - 2.0f * g0, 0.0f);
            float sq1 = fmaxf(nr + nc1 - 2.0f * g1, 0.0f);
            float sq2 = fmaxf(nr + nc2 - 2.0f * g2, 0.0f);
            float sq3 = fmaxf(nr + nc3 - 2.0f * g3, 0.0f);
            float4 dd;
            dd.x = (sq0 > 0.0f) ? sqrtf(sq0) : 0.0f;
            dd.y = (sq1 > 0.0f) ? sqrtf(sq1) : 0.0f;
            dd.z = (sq2 > 0.0f) ? sqrtf(sq2) : 0.0f;
            dd.w = (sq3 > 0.0f) ? sqrtf(sq3) : 0.0f;
            tmax = fmaxf(tmax, fmaxf(fmaxf(dd.x, dd.y), fmaxf(dd.z, dd.w)));
            *(float4*)&dist[(size_t)r * N + colg] = dd;
            tcol[0][i] = dd.x; tcol[1][i] = dd.y;
            tcol[2][i] = dd.z; tcol[3][i] = dd.w;
        }
        if (offdiag) {
            const int rb = y0 + ty * 8;
#pragma unroll
            for (int j = 0; j < 4; j++) {
                *(float4*)&dist[(size_t)(colg + j) * N + rb]     = *(float4*)&tcol[j][0];
                *(float4*)&dist[(size_t)(colg + j) * N + rb + 4] = *(float4*)&tcol[j][4];
            }
        }
    }

    fred[tid] = tmax;
    __syncthreads();
    for (int off = 128; off > 0; off >>= 1) {
        if (tid < off) fred[tid] = fmaxf(fred[tid], fred[tid + off]);
        __syncthreads();
    }
    if (tid == 0) atomicMax(&g_maxbits[which], __float_as_uint(fred[0]));
}

// ---------------- per-row ranking: 10-bit combined-key keys-only sort -------
// RT=512, IPT=8: same total sort work as 256x16 but ~half the per-thread
// register state => 2 resident blocks = 32 warps/SM (2x occupancy).
// Ranks bit-identical to R16 => ranksum fingerprint 7.735759e-05 must hold.
constexpr int RT  = 512;
constexpr int IPT = 8;
using Sorter = cub::BlockRadixSort<unsigned int, RT, IPT, cub::NullType, 5>;

__global__ __launch_bounds__(RT) void rank_kernel() {
    __shared__ typename Sorter::TempStorage sort_tmp;
    __shared__ unsigned short rank_x[N];
    __shared__ int    ired[RT];
    __shared__ double dred[RT];

    const int row  = blockIdx.x;
    const int tid  = threadIdx.x;
    const int base = tid * IPT;
    const float invx = 1023.0f / __uint_as_float(g_maxbits[0]);
    const float invz = 1023.0f / __uint_as_float(g_maxbits[1]);

    unsigned int keys[IPT];
    float dxv[IPT];

    // ---- phase 1: rank_x
    {
        const float* rowp = g_dist_x + (size_t)row * N + base;
#pragma unroll
        for (int q = 0; q < IPT / 4; q++) {
            float4 v = *(const float4*)(rowp + q * 4);
            float vv[4] = {v.x, v.y, v.z, v.w};
#pragma unroll
            for (int c = 0; c < 4; c++) {
                int i  = q * 4 + c;
                dxv[i] = vv[c];
                unsigned int qk = (unsigned int)fminf(vv[c] * invx, 1023.0f);
                keys[i] = (qk << 12) | (unsigned int)(base + i);
            }
        }
        Sorter(sort_tmp).Sort(keys, 12, 22);
        __syncthreads();
#pragma unroll
        for (int i = 0; i < IPT; i++)
            rank_x[keys[i] & 0xfffu] = (unsigned short)(base + i);
        __syncthreads();
    }

    // ---- phase 2: rank_z + |diff| + pairdist
    float psumf = 0.f;
    {
        const float* rowp = g_dist_z + (size_t)row * N + base;
#pragma unroll
        for (int q = 0; q < IPT / 4; q++) {
            float4 v = *(const float4*)(rowp + q * 4);
            float vv[4] = {v.x, v.y, v.z, v.w};
#pragma unroll
            for (int c = 0; c < 4; c++) {
                int i   = q * 4 + c;
                float e = vv[c] - dxv[i];
                psumf  += e * e;
                unsigned int qk = (unsigned int)fminf(vv[c] * invz, 1023.0f);
                keys[i] = (qk << 12) | (unsigned int)(base + i);
            }
        }
        Sorter(sort_tmp).Sort(keys, 12, 22);
        __syncthreads();

        int acc = 0;
#pragma unroll
        for (int i = 0; i < IPT; i++) {
            int p = base + i;                          // rank_z
            int q = (int)rank_x[keys[i] & 0xfffu];     // rank_x of same element
            int d = p - q;
            acc += (d < 0) ? -d : d;
        }
        ired[tid] = acc;
        dred[tid] = (double)psumf;
        __syncthreads();
        for (int off = RT / 2; off > 0; off >>= 1) {
            if (tid < off) {
                ired[tid] += ired[tid + off];
                dred[tid] += dred[tid + off];
            }
            __syncthreads();
        }
        if (tid == 0) {
            atomicAdd(&g_ranksum, (unsigned long long)ired[0]);
            g_partials[row] = dred[0];
        }
    }
}

// ---------------- finalize --------------------------------------------------
__global__ void finalize_kernel(float* __restrict__ out, int out_size) {
    __shared__ double red[256];
    int tid = threadIdx.x;
    double s = 0.0;
    for (int i = tid; i < N; i += 256) s += g_partials[i];
    red[tid] = s;
    __syncthreads();
    for (int off = 128; off > 0; off >>= 1) {
        if (tid < off) red[tid] += red[tid + off];
        __syncthreads();
    }
    if (tid == 0) {
        double nn        = (double)N * (double)N;
        double pairdist  = red[0] / nn;
        double rank_loss = ((double)g_ranksum / nn) / KDIV;
        double total     = rank_loss + LPAIR * pairdist;
        if (out_size > 0) out[0] = (float)total;
        if (out_size > 1) out[1] = (float)rank_loss;
        if (out_size > 2) out[2] = (float)pairdist;
    }
}

// ---------------- launch ----------------------------------------------------
extern "C" void kernel_launch(void* const* d_in, const int* in_sizes, int n_in,
                              void* d_out, int out_size) {
    const float* x = (const float*)d_in[0];
    const float* z = (const float*)d_in[1];

    transpose_kernel<<<dim3(DX / 32 + DZ / 32, N / 32), dim3(32, 8)>>>(x, z);
    norms_kernel<<<2 * N, 128>>>(x, z);

    dist_kernel<<<2 * NBLK, 256>>>();

    rank_kernel<<<N, RT>>>();

    finalize_kernel<<<1, 256>>>((float*)d_out, out_size);
}